// round 10
// baseline (speedup 1.0000x reference)
#include <cuda_runtime.h>
#include <cuda_fp16.h>
#include <cstdint>
#include <cstddef>

// Problem dims (fixed by reference)
#define Bb 256
#define Tt 512
#define Dd 64
#define Ll 32
#define Hh 128
#define G4 512   // 4*H

// ---------------- scratch (device globals; no allocation allowed) ----------
__device__ float g_pre[(size_t)Bb * Tt * G4];   // 268 MB: pre-activations

// ---------------- math helpers ---------------------------------------------
__device__ __forceinline__ float sigf(float x) {
    return __fdividef(1.0f, 1.0f + __expf(-x));
}
__device__ __forceinline__ float tanhf_fast(float x) {
    x = fminf(20.0f, fmaxf(-20.0f, x));
    float e = __expf(-2.0f * x);
    return __fdividef(1.0f - e, 1.0f + e);
}

// ============================================================================
// Kernel 1: pre-GEMM with fused static part (unchanged — proven).
// ============================================================================
#define PRE_MT 64
#define PRE_NT 128
#define PRE_PAD 65
#define PRE_SMEM (((PRE_MT + PRE_NT) * PRE_PAD + PRE_NT) * 4)   // 50432 bytes

__global__ __launch_bounds__(256) void pre_kernel(
    const float* __restrict__ xd, const float* __restrict__ Wih,
    const float* __restrict__ xs, const float* __restrict__ Wzh,
    const float* __restrict__ bvec)
{
    extern __shared__ float sm[];
    float* xsm   = sm;                                  // [64][65]
    float* wsm   = sm + PRE_MT * PRE_PAD;               // [128][65]
    float* svrow = sm + (PRE_MT + PRE_NT) * PRE_PAD;    // [128]

    int t  = threadIdx.x;
    int m0 = blockIdx.x * PRE_MT;
    int n0 = blockIdx.y * PRE_NT;
    int bb = m0 >> 9;   // T = 512

    {
        const float4* xg = (const float4*)(xd + (size_t)m0 * Dd);
        for (int i = t; i < PRE_MT * (Dd / 4); i += 256) {
            int row = i >> 4, dq = i & 15;
            float4 v = xg[row * 16 + dq];
            float* dst = xsm + row * PRE_PAD + dq * 4;
            dst[0] = v.x; dst[1] = v.y; dst[2] = v.z; dst[3] = v.w;
        }
    }
    {
        const float4* wg = (const float4*)(Wih + (size_t)n0 * Dd);
        for (int i = t; i < PRE_NT * (Dd / 4); i += 256) {
            int row = i >> 4, dq = i & 15;
            float4 v = wg[row * 16 + dq];
            float* dst = wsm + row * PRE_PAD + dq * 4;
            dst[0] = v.x; dst[1] = v.y; dst[2] = v.z; dst[3] = v.w;
        }
    }
    if (t < PRE_NT) {
        int gn = n0 + t;
        float acc = bvec[gn];
        const float* w = Wzh + gn * Ll;
        const float* xr = xs + bb * Ll;
#pragma unroll
        for (int l = 0; l < Ll; l++) acc += xr[l] * w[l];
        svrow[t] = acc;
    }
    __syncthreads();

    int tn = t & 15;
    int tm = t >> 4;

    float acc[4][8];
#pragma unroll
    for (int i = 0; i < 4; i++)
#pragma unroll
        for (int jj = 0; jj < 8; jj++) acc[i][jj] = 0.0f;

#pragma unroll 8
    for (int k = 0; k < Dd; k++) {
        float a[4], b[8];
#pragma unroll
        for (int i = 0; i < 4; i++)  a[i]  = xsm[(tm + 16 * i) * PRE_PAD + k];
#pragma unroll
        for (int jj = 0; jj < 8; jj++) b[jj] = wsm[(tn + 16 * jj) * PRE_PAD + k];
#pragma unroll
        for (int i = 0; i < 4; i++)
#pragma unroll
            for (int jj = 0; jj < 8; jj++) acc[i][jj] += a[i] * b[jj];
    }

    float sv[8];
#pragma unroll
    for (int jj = 0; jj < 8; jj++) sv[jj] = svrow[tn + 16 * jj];
#pragma unroll
    for (int i = 0; i < 4; i++) {
        float* orow = g_pre + (size_t)(m0 + tm + 16 * i) * G4 + n0;
#pragma unroll
        for (int jj = 0; jj < 8; jj++) orow[tn + 16 * jj] = acc[i][jj] + sv[jj];
    }
}

// ============================================================================
// Kernel 2: persistent LSTM scan — OCCUPANCY round.
//   256 CTAs x ONE batch row, __launch_bounds__(512, 2) -> 2 independent
//   CTAs per SM (8 warps/SMSP).  When one CTA is in its barrier/update tail,
//   the other's matvec warps fill the issue slots.  Same fp16-W arithmetic
//   per row as R9 (d 0..95 fp16 smem; d 96..127 fp16 in 16 half2 registers,
//   converted per step on the idle ALU pipe).  Activations computed by all
//   512 matvec threads (warp-uniform select).  smem 98.5KB/CTA -> 2 fit.
// ============================================================================
#define NWCH 12   // fp16 W chunks of 8 d-values (d 0..95)
// float-index offsets within dynamic smem
#define OFF_WH   0                        // 12*512*8 halfs = 24576 floats
#define OFF_H    24576                    // h[128] fp32
#define OFF_G    (OFF_H + 128)            // act[512]
#define OFF_RED  (OFF_G + 512)            // red[4]
#define SCAN_SMEM ((OFF_RED + 4) * 4)     // 100880 bytes

__global__ void __launch_bounds__(512, 2)
scan_kernel(const float* __restrict__ Whh, const float* __restrict__ Wout,
            const float* __restrict__ bout, float* __restrict__ out)
{
    extern __shared__ float sm[];
    __half* whsm = (__half*)(sm + OFF_WH);   // [12 chunks][512 j][8 d] fp16
    int tid = threadIdx.x;
    int b0  = blockIdx.x;          // ONE batch row per CTA
    int j   = tid;                 // gate-column index 0..511
    bool is_tanh_gate = ((j >> 7) == 2);   // warp-uniform

    // ---- W d 0..95 -> fp16 smem: whsm[c][j][0..7]
#pragma unroll
    for (int c = 0; c < NWCH; c++) {
        float4 va = *(const float4*)(Whh + (size_t)j * 128 + c * 8);
        float4 vb = *(const float4*)(Whh + (size_t)j * 128 + c * 8 + 4);
        __half2 p0 = __floats2half2_rn(va.x, va.y);
        __half2 p1 = __floats2half2_rn(va.z, va.w);
        __half2 p2 = __floats2half2_rn(vb.x, vb.y);
        __half2 p3 = __floats2half2_rn(vb.z, vb.w);
        uint4 pk;
        pk.x = *(uint32_t*)&p0; pk.y = *(uint32_t*)&p1;
        pk.z = *(uint32_t*)&p2; pk.w = *(uint32_t*)&p3;
        *(uint4*)(whsm + (size_t)c * 4096 + j * 8) = pk;
    }
    // ---- W d 96..127 as 16 half2 registers (reg diet for 2 CTAs/SM)
    __half2 whr[16];
    {
        const float* ws = Whh + (size_t)j * 128 + 96;
#pragma unroll
        for (int c = 0; c < 16; c++)
            whr[c] = __floats2half2_rn(ws[2 * c], ws[2 * c + 1]);
    }
    if (tid < 128) sm[OFF_H + tid] = 0.0f;
    __syncthreads();

    int k = tid & 127;        // hidden index (update role, tid < 128)

    float cst = 0.0f;
    float wo  = (tid < 128) ? Wout[k] : 0.0f;
    float bo  = bout[0];

    const float* prep = g_pre + ((size_t)b0 * Tt) * G4 + j;
    const float* hsh  = sm + OFF_H;

    for (int t = 0; t < Tt; t++) {
        float p = prep[(size_t)t * G4];

        // matvec (one row): two alternating accumulator chains
        float accA = 0.0f, accB = 0.0f;
#pragma unroll
        for (int c = 0; c < NWCH; c += 2) {      // d 0..95 (fp16 smem weights)
            {
                uint4 pk = *(const uint4*)(whsm + (size_t)c * 4096 + j * 8);
                float2 w0 = __half22float2(*(__half2*)&pk.x);
                float2 w1 = __half22float2(*(__half2*)&pk.y);
                float2 w2 = __half22float2(*(__half2*)&pk.z);
                float2 w3 = __half22float2(*(__half2*)&pk.w);
                float4 ha = *(const float4*)(hsh + c * 8);
                float4 hb = *(const float4*)(hsh + c * 8 + 4);
                accA += w0.x * ha.x + w0.y * ha.y + w1.x * ha.z + w1.y * ha.w
                      + w2.x * hb.x + w2.y * hb.y + w3.x * hb.z + w3.y * hb.w;
            }
            {
                uint4 pk = *(const uint4*)(whsm + (size_t)(c + 1) * 4096 + j * 8);
                float2 w0 = __half22float2(*(__half2*)&pk.x);
                float2 w1 = __half22float2(*(__half2*)&pk.y);
                float2 w2 = __half22float2(*(__half2*)&pk.z);
                float2 w3 = __half22float2(*(__half2*)&pk.w);
                float4 ha = *(const float4*)(hsh + (c + 1) * 8);
                float4 hb = *(const float4*)(hsh + (c + 1) * 8 + 4);
                accB += w0.x * ha.x + w0.y * ha.y + w1.x * ha.z + w1.y * ha.w
                      + w2.x * hb.x + w2.y * hb.y + w3.x * hb.z + w3.y * hb.w;
            }
        }
#pragma unroll
        for (int i = 0; i < 4; i++) {            // d 96..127 (half2 registers)
            float2 w0 = __half22float2(whr[4 * i + 0]);
            float2 w1 = __half22float2(whr[4 * i + 1]);
            float2 w2 = __half22float2(whr[4 * i + 2]);
            float2 w3 = __half22float2(whr[4 * i + 3]);
            float4 ha = *(const float4*)(hsh + 96 + i * 8);
            float4 hb = *(const float4*)(hsh + 96 + i * 8 + 4);
            float* acc = (i & 1) ? &accB : &accA;
            *acc += w0.x * ha.x + w0.y * ha.y + w1.x * ha.z + w1.y * ha.w
                  + w2.x * hb.x + w2.y * hb.y + w3.x * hb.z + w3.y * hb.w;
        }
        float g = p + (accA + accB);

        // gate activation in the matvec threads (warp-uniform branch)
        float act = is_tanh_gate ? tanhf_fast(g) : sigf(g);
        sm[OFF_G + j] = act;
        __syncthreads();

        // state update (threads 0..127)
        if (tid < 128) {
            float ai = sm[OFF_G + k];
            float af = sm[OFF_G + 128 + k];
            float ag = sm[OFF_G + 256 + k];
            float ao = sm[OFF_G + 384 + k];
            cst = af * cst + ai * ag;
            float hval = ao * tanhf_fast(cst);
            sm[OFF_H + k] = hval;

            // fused O=1 head: warp-reduce hval*wo (warps 0..3)
            float v = hval * wo;
            v += __shfl_down_sync(0xffffffffu, v, 16);
            v += __shfl_down_sync(0xffffffffu, v, 8);
            v += __shfl_down_sync(0xffffffffu, v, 4);
            v += __shfl_down_sync(0xffffffffu, v, 2);
            v += __shfl_down_sync(0xffffffffu, v, 1);
            if ((tid & 31) == 0) sm[OFF_RED + (tid >> 5)] = v;
        }
        __syncthreads();   // h + red ready; fences act[] overwrite

        if (tid == 0) {
            const float* rd = sm + OFF_RED;
            out[(size_t)b0 * Tt + t] = rd[0] + rd[1] + rd[2] + rd[3] + bo;
        }
    }
}

// ============================================================================
// launch
// ============================================================================
extern "C" void kernel_launch(void* const* d_in, const int* in_sizes, int n_in,
                              void* d_out, int out_size)
{
    const float* x_dyn = (const float*)d_in[0];
    const float* x_sta = (const float*)d_in[1];
    const float* W_ih  = (const float*)d_in[2];
    const float* W_hh  = (const float*)d_in[3];
    const float* W_zh  = (const float*)d_in[4];
    const float* bvec  = (const float*)d_in[5];
    const float* W_out = (const float*)d_in[6];
    const float* b_out = (const float*)d_in[7];
    float* out = (float*)d_out;

    (void)in_sizes; (void)n_in; (void)out_size;

    cudaFuncSetAttribute(pre_kernel,
                         cudaFuncAttributeMaxDynamicSharedMemorySize, PRE_SMEM);
    cudaFuncSetAttribute(scan_kernel,
                         cudaFuncAttributeMaxDynamicSharedMemorySize, SCAN_SMEM);

    dim3 pre_grid((Bb * Tt) / PRE_MT, G4 / PRE_NT);   // 2048 x 4
    pre_kernel<<<pre_grid, 256, PRE_SMEM>>>(x_dyn, W_ih, x_sta, W_zh, bvec);

    scan_kernel<<<Bb, 512, SCAN_SMEM>>>(W_hh, W_out, b_out, out);
}

// round 11
// speedup vs baseline: 1.6265x; 1.6265x over previous
#include <cuda_runtime.h>
#include <cuda_fp16.h>
#include <cstdint>
#include <cstddef>

// Problem dims (fixed by reference)
#define Bb 256
#define Tt 512
#define Dd 64
#define Ll 32
#define Hh 128
#define G4 512   // 4*H

// ---------------- scratch (device globals; no allocation allowed) ----------
__device__ float g_pre[(size_t)Bb * Tt * G4];   // 268 MB: pre-activations

// ---------------- math helpers ---------------------------------------------
__device__ __forceinline__ float sigf(float x) {
    return __fdividef(1.0f, 1.0f + __expf(-x));
}
__device__ __forceinline__ float tanhf_fast(float x) {
    x = fminf(20.0f, fmaxf(-20.0f, x));
    float e = __expf(-2.0f * x);
    return __fdividef(1.0f - e, 1.0f + e);
}

// ============================================================================
// Kernel 1: pre-GEMM with fused static part (unchanged — proven).
// ============================================================================
#define PRE_MT 64
#define PRE_NT 128
#define PRE_PAD 65
#define PRE_SMEM (((PRE_MT + PRE_NT) * PRE_PAD + PRE_NT) * 4)   // 50432 bytes

__global__ __launch_bounds__(256) void pre_kernel(
    const float* __restrict__ xd, const float* __restrict__ Wih,
    const float* __restrict__ xs, const float* __restrict__ Wzh,
    const float* __restrict__ bvec)
{
    extern __shared__ float sm[];
    float* xsm   = sm;                                  // [64][65]
    float* wsm   = sm + PRE_MT * PRE_PAD;               // [128][65]
    float* svrow = sm + (PRE_MT + PRE_NT) * PRE_PAD;    // [128]

    int t  = threadIdx.x;
    int m0 = blockIdx.x * PRE_MT;
    int n0 = blockIdx.y * PRE_NT;
    int bb = m0 >> 9;   // T = 512

    {
        const float4* xg = (const float4*)(xd + (size_t)m0 * Dd);
        for (int i = t; i < PRE_MT * (Dd / 4); i += 256) {
            int row = i >> 4, dq = i & 15;
            float4 v = xg[row * 16 + dq];
            float* dst = xsm + row * PRE_PAD + dq * 4;
            dst[0] = v.x; dst[1] = v.y; dst[2] = v.z; dst[3] = v.w;
        }
    }
    {
        const float4* wg = (const float4*)(Wih + (size_t)n0 * Dd);
        for (int i = t; i < PRE_NT * (Dd / 4); i += 256) {
            int row = i >> 4, dq = i & 15;
            float4 v = wg[row * 16 + dq];
            float* dst = wsm + row * PRE_PAD + dq * 4;
            dst[0] = v.x; dst[1] = v.y; dst[2] = v.z; dst[3] = v.w;
        }
    }
    if (t < PRE_NT) {
        int gn = n0 + t;
        float acc = bvec[gn];
        const float* w = Wzh + gn * Ll;
        const float* xr = xs + bb * Ll;
#pragma unroll
        for (int l = 0; l < Ll; l++) acc += xr[l] * w[l];
        svrow[t] = acc;
    }
    __syncthreads();

    int tn = t & 15;
    int tm = t >> 4;

    float acc[4][8];
#pragma unroll
    for (int i = 0; i < 4; i++)
#pragma unroll
        for (int jj = 0; jj < 8; jj++) acc[i][jj] = 0.0f;

#pragma unroll 8
    for (int k = 0; k < Dd; k++) {
        float a[4], b[8];
#pragma unroll
        for (int i = 0; i < 4; i++)  a[i]  = xsm[(tm + 16 * i) * PRE_PAD + k];
#pragma unroll
        for (int jj = 0; jj < 8; jj++) b[jj] = wsm[(tn + 16 * jj) * PRE_PAD + k];
#pragma unroll
        for (int i = 0; i < 4; i++)
#pragma unroll
            for (int jj = 0; jj < 8; jj++) acc[i][jj] += a[i] * b[jj];
    }

    float sv[8];
#pragma unroll
    for (int jj = 0; jj < 8; jj++) sv[jj] = svrow[tn + 16 * jj];
#pragma unroll
    for (int i = 0; i < 4; i++) {
        float* orow = g_pre + (size_t)(m0 + tm + 16 * i) * G4 + n0;
#pragma unroll
        for (int jj = 0; jj < 8; jj++) orow[tn + 16 * jj] = acc[i][jj] + sv[jj];
    }
}

// ============================================================================
// Kernel 2: persistent LSTM scan — HFMA2 round.
//   R9 winning shape (128 CTAs x 512 threads x 2 rows; W amortized over both
//   rows; activations in the update phase; 2 barriers) with the FMA floor cut:
//   - W d0..95 fp16 smem (as R9), d96..127 fp16 in 16 half2 registers
//   - h state stored fp16 (h16[2][128]) -> h-load instructions halved
//   - matvec in HFMA2: 2 d-values per instruction -> 128 HFMA2 vs 256 FFMA
//   - per row, accumulation split across 4 half2 accumulators (8 fp16 lanes
//     x 16 terms) -> gate pre-act abs err ~3e-4; merged in fp32; cst fp32
// ============================================================================
#define NWCH 12   // fp16 W chunks of 8 d-values (d 0..95)
// float-index offsets within dynamic smem
#define OFF_WH   0                        // 12*512*8 halfs = 24576 floats
#define OFF_H16  24576                    // h16[2][128] fp16 = 128 floats
#define OFF_G    (OFF_H16 + 128)          // g[2][512] fp32 pre-acts
#define OFF_RED  (OFF_G + 1024)           // red[8]
#define SCAN_SMEM ((OFF_RED + 8) * 4)     // 102944 bytes

__global__ void __launch_bounds__(512, 1)
scan_kernel(const float* __restrict__ Whh, const float* __restrict__ Wout,
            const float* __restrict__ bout, float* __restrict__ out)
{
    extern __shared__ float sm[];
    __half* whsm = (__half*)(sm + OFF_WH);    // [12 chunks][512 j][8 d] fp16
    __half* h16  = (__half*)(sm + OFF_H16);   // [2 rows][128 d] fp16
    int tid = threadIdx.x;
    int b0  = blockIdx.x * 2;
    int j   = tid;                 // gate-column index 0..511

    // ---- W d 0..95 -> fp16 smem: whsm[c][j][0..7]
#pragma unroll
    for (int c = 0; c < NWCH; c++) {
        float4 va = *(const float4*)(Whh + (size_t)j * 128 + c * 8);
        float4 vb = *(const float4*)(Whh + (size_t)j * 128 + c * 8 + 4);
        __half2 p0 = __floats2half2_rn(va.x, va.y);
        __half2 p1 = __floats2half2_rn(va.z, va.w);
        __half2 p2 = __floats2half2_rn(vb.x, vb.y);
        __half2 p3 = __floats2half2_rn(vb.z, vb.w);
        uint4 pk;
        pk.x = *(uint32_t*)&p0; pk.y = *(uint32_t*)&p1;
        pk.z = *(uint32_t*)&p2; pk.w = *(uint32_t*)&p3;
        *(uint4*)(whsm + (size_t)c * 4096 + j * 8) = pk;
    }
    // ---- W d 96..127 as 16 half2 registers (d pairs 96,97 .. 126,127)
    __half2 whr[16];
    {
        const float* ws = Whh + (size_t)j * 128 + 96;
#pragma unroll
        for (int c = 0; c < 16; c++)
            whr[c] = __floats2half2_rn(ws[2 * c], ws[2 * c + 1]);
    }
    if (tid < 256) h16[tid] = __float2half(0.0f);
    __syncthreads();

    int r2 = tid >> 7;        // row 0..1 (update role, tid < 256)
    int k  = tid & 127;       // hidden index (update role)

    float cst = 0.0f;
    float wo  = (tid < 256) ? Wout[k] : 0.0f;
    float bo  = bout[0];

    const float* pre0 = g_pre + ((size_t)(b0 + 0) * Tt) * G4 + j;
    const float* pre1 = g_pre + ((size_t)(b0 + 1) * Tt) * G4 + j;

    const __half2 z2 = __float2half2_rn(0.0f);

    for (int t = 0; t < Tt; t++) {
        float p0 = pre0[(size_t)t * G4];
        float p1 = pre1[(size_t)t * G4];

        // matvec in HFMA2: per row, 4 half2 accumulators (8 lanes x 16 terms)
        __half2 acc0[4], acc1[4];
#pragma unroll
        for (int i = 0; i < 4; i++) { acc0[i] = z2; acc1[i] = z2; }

#pragma unroll
        for (int c = 0; c < NWCH; c++) {         // d 0..95 (fp16 smem weights)
            uint4 wp  = *(const uint4*)(whsm + (size_t)c * 4096 + j * 8);
            uint4 hp0 = *(const uint4*)(h16 + c * 8);          // row 0, d 8c..8c+7
            uint4 hp1 = *(const uint4*)(h16 + 128 + c * 8);    // row 1
            const __half2* w2 = (const __half2*)&wp;
            const __half2* a2 = (const __half2*)&hp0;
            const __half2* b2 = (const __half2*)&hp1;
            int ai = c & 3;
#pragma unroll
            for (int q = 0; q < 4; q++) {
                acc0[ai] = __hfma2(w2[q], a2[q], acc0[ai]);
                acc1[ai] = __hfma2(w2[q], b2[q], acc1[ai]);
            }
        }
#pragma unroll
        for (int c = 0; c < 4; c++) {            // d 96..127 (register weights)
            uint4 hp0 = *(const uint4*)(h16 + 96 + c * 8);
            uint4 hp1 = *(const uint4*)(h16 + 128 + 96 + c * 8);
            const __half2* a2 = (const __half2*)&hp0;
            const __half2* b2 = (const __half2*)&hp1;
#pragma unroll
            for (int q = 0; q < 4; q++) {
                acc0[c] = __hfma2(whr[4 * c + q], a2[q], acc0[c]);
                acc1[c] = __hfma2(whr[4 * c + q], b2[q], acc1[c]);
            }
        }
        // merge 8 fp16 lanes per row in fp32
        float2 m00 = __half22float2(acc0[0]), m01 = __half22float2(acc0[1]);
        float2 m02 = __half22float2(acc0[2]), m03 = __half22float2(acc0[3]);
        float2 m10 = __half22float2(acc1[0]), m11 = __half22float2(acc1[1]);
        float2 m12 = __half22float2(acc1[2]), m13 = __half22float2(acc1[3]);
        float g0 = p0 + ((m00.x + m00.y) + (m01.x + m01.y))
                      + ((m02.x + m02.y) + (m03.x + m03.y));
        float g1 = p1 + ((m10.x + m10.y) + (m11.x + m11.y))
                      + ((m12.x + m12.y) + (m13.x + m13.y));

        // stage full gate pre-activations (fp32)
        sm[OFF_G + 0 * 512 + j] = g0;
        sm[OFF_G + 1 * 512 + j] = g1;
        __syncthreads();

        // state update (threads 0..255: 2 rows x 128 hidden)
        if (tid < 256) {
            float gi = sm[OFF_G + r2 * 512 + k];
            float gf = sm[OFF_G + r2 * 512 + 128 + k];
            float gc = sm[OFF_G + r2 * 512 + 256 + k];
            float go = sm[OFF_G + r2 * 512 + 384 + k];
            cst = sigf(gf) * cst + sigf(gi) * tanhf_fast(gc);
            float hval = sigf(go) * tanhf_fast(cst);
            h16[r2 * 128 + k] = __float2half(hval);

            // fused O=1 head: warp-reduce hval*wo (warps 0..7)
            float v = hval * wo;
            v += __shfl_down_sync(0xffffffffu, v, 16);
            v += __shfl_down_sync(0xffffffffu, v, 8);
            v += __shfl_down_sync(0xffffffffu, v, 4);
            v += __shfl_down_sync(0xffffffffu, v, 2);
            v += __shfl_down_sync(0xffffffffu, v, 1);
            if ((tid & 31) == 0) sm[OFF_RED + (tid >> 5)] = v;
        }
        __syncthreads();   // h16 + red ready for next step

        if (tid < 2) {
            const float* rd = sm + OFF_RED + tid * 4;
            out[(size_t)(b0 + tid) * Tt + t] = rd[0] + rd[1] + rd[2] + rd[3] + bo;
        }
    }
}

// ============================================================================
// launch
// ============================================================================
extern "C" void kernel_launch(void* const* d_in, const int* in_sizes, int n_in,
                              void* d_out, int out_size)
{
    const float* x_dyn = (const float*)d_in[0];
    const float* x_sta = (const float*)d_in[1];
    const float* W_ih  = (const float*)d_in[2];
    const float* W_hh  = (const float*)d_in[3];
    const float* W_zh  = (const float*)d_in[4];
    const float* bvec  = (const float*)d_in[5];
    const float* W_out = (const float*)d_in[6];
    const float* b_out = (const float*)d_in[7];
    float* out = (float*)d_out;

    (void)in_sizes; (void)n_in; (void)out_size;

    cudaFuncSetAttribute(pre_kernel,
                         cudaFuncAttributeMaxDynamicSharedMemorySize, PRE_SMEM);
    cudaFuncSetAttribute(scan_kernel,
                         cudaFuncAttributeMaxDynamicSharedMemorySize, SCAN_SMEM);

    dim3 pre_grid((Bb * Tt) / PRE_MT, G4 / PRE_NT);   // 2048 x 4
    pre_kernel<<<pre_grid, 256, PRE_SMEM>>>(x_dyn, W_ih, x_sta, W_zh, bvec);

    scan_kernel<<<128, 512, SCAN_SMEM>>>(W_hh, W_out, b_out, out);
}

// round 12
// speedup vs baseline: 1.6622x; 1.0220x over previous
#include <cuda_runtime.h>
#include <cuda_fp16.h>
#include <cstdint>
#include <cstddef>

// Problem dims (fixed by reference)
#define Bb 256
#define Tt 512
#define Dd 64
#define Ll 32
#define Hh 128
#define G4 512   // 4*H

// ---------------- scratch (device globals; no allocation allowed) ----------
__device__ float g_pre[(size_t)Bb * Tt * G4];   // 268 MB: pre-activations

// ---------------- math helpers ---------------------------------------------
__device__ __forceinline__ float sigf(float x) {
    return __fdividef(1.0f, 1.0f + __expf(-x));
}
__device__ __forceinline__ float tanhf_fast(float x) {
    x = fminf(20.0f, fmaxf(-20.0f, x));
    float e = __expf(-2.0f * x);
    return __fdividef(1.0f - e, 1.0f + e);
}

// ============================================================================
// Kernel 1: pre-GEMM with fused static part (unchanged — proven).
// ============================================================================
#define PRE_MT 64
#define PRE_NT 128
#define PRE_PAD 65
#define PRE_SMEM (((PRE_MT + PRE_NT) * PRE_PAD + PRE_NT) * 4)   // 50432 bytes

__global__ __launch_bounds__(256) void pre_kernel(
    const float* __restrict__ xd, const float* __restrict__ Wih,
    const float* __restrict__ xs, const float* __restrict__ Wzh,
    const float* __restrict__ bvec)
{
    extern __shared__ float sm[];
    float* xsm   = sm;                                  // [64][65]
    float* wsm   = sm + PRE_MT * PRE_PAD;               // [128][65]
    float* svrow = sm + (PRE_MT + PRE_NT) * PRE_PAD;    // [128]

    int t  = threadIdx.x;
    int m0 = blockIdx.x * PRE_MT;
    int n0 = blockIdx.y * PRE_NT;
    int bb = m0 >> 9;   // T = 512

    {
        const float4* xg = (const float4*)(xd + (size_t)m0 * Dd);
        for (int i = t; i < PRE_MT * (Dd / 4); i += 256) {
            int row = i >> 4, dq = i & 15;
            float4 v = xg[row * 16 + dq];
            float* dst = xsm + row * PRE_PAD + dq * 4;
            dst[0] = v.x; dst[1] = v.y; dst[2] = v.z; dst[3] = v.w;
        }
    }
    {
        const float4* wg = (const float4*)(Wih + (size_t)n0 * Dd);
        for (int i = t; i < PRE_NT * (Dd / 4); i += 256) {
            int row = i >> 4, dq = i & 15;
            float4 v = wg[row * 16 + dq];
            float* dst = wsm + row * PRE_PAD + dq * 4;
            dst[0] = v.x; dst[1] = v.y; dst[2] = v.z; dst[3] = v.w;
        }
    }
    if (t < PRE_NT) {
        int gn = n0 + t;
        float acc = bvec[gn];
        const float* w = Wzh + gn * Ll;
        const float* xr = xs + bb * Ll;
#pragma unroll
        for (int l = 0; l < Ll; l++) acc += xr[l] * w[l];
        svrow[t] = acc;
    }
    __syncthreads();

    int tn = t & 15;
    int tm = t >> 4;

    float acc[4][8];
#pragma unroll
    for (int i = 0; i < 4; i++)
#pragma unroll
        for (int jj = 0; jj < 8; jj++) acc[i][jj] = 0.0f;

#pragma unroll 8
    for (int k = 0; k < Dd; k++) {
        float a[4], b[8];
#pragma unroll
        for (int i = 0; i < 4; i++)  a[i]  = xsm[(tm + 16 * i) * PRE_PAD + k];
#pragma unroll
        for (int jj = 0; jj < 8; jj++) b[jj] = wsm[(tn + 16 * jj) * PRE_PAD + k];
#pragma unroll
        for (int i = 0; i < 4; i++)
#pragma unroll
            for (int jj = 0; jj < 8; jj++) acc[i][jj] += a[i] * b[jj];
    }

    float sv[8];
#pragma unroll
    for (int jj = 0; jj < 8; jj++) sv[jj] = svrow[tn + 16 * jj];
#pragma unroll
    for (int i = 0; i < 4; i++) {
        float* orow = g_pre + (size_t)(m0 + tm + 16 * i) * G4 + n0;
#pragma unroll
        for (int jj = 0; jj < 8; jj++) orow[tn + 16 * jj] = acc[i][jj] + sv[jj];
    }
}

// ============================================================================
// Kernel 2: persistent LSTM scan — critical-section round.
//   R11 matvec untouched (HFMA2, fp16 W smem + half2 W regs, fp16 h).
//   Changes:
//   (1) gate activations computed by all 512 matvec threads (stage act,
//       not pre-act; warp-uniform sigma/tanh select) -> update tail = 1 tanh
//   (2) O=1 head moved AFTER barrier 2, done by warps 8,9 (one full row-dot
//       each from h16) while other warps run the next matvec -> SHFL chain
//       off the critical path, no red array, still 2 barriers
// ============================================================================
#define NWCH 12   // fp16 W chunks of 8 d-values (d 0..95)
// float-index offsets within dynamic smem
#define OFF_WH   0                        // 12*512*8 halfs = 24576 floats
#define OFF_H16  24576                    // h16[2][128] fp16 = 128 floats
#define OFF_G    (OFF_H16 + 128)          // act[2][512] fp32
#define SCAN_SMEM ((OFF_G + 1024) * 4)    // 102912 bytes

__global__ void __launch_bounds__(512, 1)
scan_kernel(const float* __restrict__ Whh, const float* __restrict__ Wout,
            const float* __restrict__ bout, float* __restrict__ out)
{
    extern __shared__ float sm[];
    __half* whsm = (__half*)(sm + OFF_WH);    // [12 chunks][512 j][8 d] fp16
    __half* h16  = (__half*)(sm + OFF_H16);   // [2 rows][128 d] fp16
    int tid  = threadIdx.x;
    int b0   = blockIdx.x * 2;
    int j    = tid;                // gate-column index 0..511
    int wrp  = tid >> 5;
    int lane = tid & 31;
    bool is_tanh_gate = ((j >> 7) == 2);   // warp-uniform

    // ---- W d 0..95 -> fp16 smem: whsm[c][j][0..7]
#pragma unroll
    for (int c = 0; c < NWCH; c++) {
        float4 va = *(const float4*)(Whh + (size_t)j * 128 + c * 8);
        float4 vb = *(const float4*)(Whh + (size_t)j * 128 + c * 8 + 4);
        __half2 p0 = __floats2half2_rn(va.x, va.y);
        __half2 p1 = __floats2half2_rn(va.z, va.w);
        __half2 p2 = __floats2half2_rn(vb.x, vb.y);
        __half2 p3 = __floats2half2_rn(vb.z, vb.w);
        uint4 pk;
        pk.x = *(uint32_t*)&p0; pk.y = *(uint32_t*)&p1;
        pk.z = *(uint32_t*)&p2; pk.w = *(uint32_t*)&p3;
        *(uint4*)(whsm + (size_t)c * 4096 + j * 8) = pk;
    }
    // ---- W d 96..127 as 16 half2 registers
    __half2 whr[16];
    {
        const float* ws = Whh + (size_t)j * 128 + 96;
#pragma unroll
        for (int c = 0; c < 16; c++)
            whr[c] = __floats2half2_rn(ws[2 * c], ws[2 * c + 1]);
    }
    if (tid < 256) h16[tid] = __float2half(0.0f);
    __syncthreads();

    int r2 = tid >> 7;        // row 0..1 (update role, tid < 256)
    int k  = tid & 127;       // hidden index (update role)

    float cst = 0.0f;
    float bo  = bout[0];
    // O-head operand registers (warps 8,9 only): Wout[lane*4 .. +3]
    float4 wo4 = make_float4(0.f, 0.f, 0.f, 0.f);
    if (wrp == 8 || wrp == 9) wo4 = *(const float4*)(Wout + lane * 4);

    const float* pre0 = g_pre + ((size_t)(b0 + 0) * Tt) * G4 + j;
    const float* pre1 = g_pre + ((size_t)(b0 + 1) * Tt) * G4 + j;

    const __half2 z2 = __float2half2_rn(0.0f);

    for (int t = 0; t < Tt; t++) {
        float p0 = pre0[(size_t)t * G4];
        float p1 = pre1[(size_t)t * G4];

        // matvec in HFMA2 (R11 body, unchanged)
        __half2 acc0[4], acc1[4];
#pragma unroll
        for (int i = 0; i < 4; i++) { acc0[i] = z2; acc1[i] = z2; }

#pragma unroll
        for (int c = 0; c < NWCH; c++) {         // d 0..95 (fp16 smem weights)
            uint4 wp  = *(const uint4*)(whsm + (size_t)c * 4096 + j * 8);
            uint4 hp0 = *(const uint4*)(h16 + c * 8);
            uint4 hp1 = *(const uint4*)(h16 + 128 + c * 8);
            const __half2* w2 = (const __half2*)&wp;
            const __half2* a2 = (const __half2*)&hp0;
            const __half2* b2 = (const __half2*)&hp1;
            int ai = c & 3;
#pragma unroll
            for (int q = 0; q < 4; q++) {
                acc0[ai] = __hfma2(w2[q], a2[q], acc0[ai]);
                acc1[ai] = __hfma2(w2[q], b2[q], acc1[ai]);
            }
        }
#pragma unroll
        for (int c = 0; c < 4; c++) {            // d 96..127 (register weights)
            uint4 hp0 = *(const uint4*)(h16 + 96 + c * 8);
            uint4 hp1 = *(const uint4*)(h16 + 128 + 96 + c * 8);
            const __half2* a2 = (const __half2*)&hp0;
            const __half2* b2 = (const __half2*)&hp1;
#pragma unroll
            for (int q = 0; q < 4; q++) {
                acc0[c] = __hfma2(whr[4 * c + q], a2[q], acc0[c]);
                acc1[c] = __hfma2(whr[4 * c + q], b2[q], acc1[c]);
            }
        }
        float2 m00 = __half22float2(acc0[0]), m01 = __half22float2(acc0[1]);
        float2 m02 = __half22float2(acc0[2]), m03 = __half22float2(acc0[3]);
        float2 m10 = __half22float2(acc1[0]), m11 = __half22float2(acc1[1]);
        float2 m12 = __half22float2(acc1[2]), m13 = __half22float2(acc1[3]);
        float g0 = p0 + ((m00.x + m00.y) + (m01.x + m01.y))
                      + ((m02.x + m02.y) + (m03.x + m03.y));
        float g1 = p1 + ((m10.x + m10.y) + (m11.x + m11.y))
                      + ((m12.x + m12.y) + (m13.x + m13.y));

        // gate activation in the matvec threads (warp-uniform branch)
        float act0, act1;
        if (is_tanh_gate) { act0 = tanhf_fast(g0); act1 = tanhf_fast(g1); }
        else              { act0 = sigf(g0);       act1 = sigf(g1);       }
        sm[OFF_G + 0 * 512 + j] = act0;
        sm[OFF_G + 1 * 512 + j] = act1;
        __syncthreads();   // barrier 1: acts visible

        // minimal critical section: state update (threads 0..255)
        if (tid < 256) {
            float ai = sm[OFF_G + r2 * 512 + k];
            float af = sm[OFF_G + r2 * 512 + 128 + k];
            float ag = sm[OFF_G + r2 * 512 + 256 + k];
            float ao = sm[OFF_G + r2 * 512 + 384 + k];
            cst = af * cst + ai * ag;
            float hval = ao * tanhf_fast(cst);
            h16[r2 * 128 + k] = __float2half(hval);
        }
        __syncthreads();   // barrier 2: h16 ready

        // O=1 head OFF the critical path: warps 8,9 compute one row each
        // from h16 while the other 14 warps proceed into step t+1's matvec.
        if (wrp == 8 || wrp == 9) {
            int row = wrp - 8;
            float2 ha = __half22float2(*(const __half2*)(h16 + row * 128 + lane * 4));
            float2 hb = __half22float2(*(const __half2*)(h16 + row * 128 + lane * 4 + 2));
            float v = ha.x * wo4.x + ha.y * wo4.y + hb.x * wo4.z + hb.y * wo4.w;
            v += __shfl_down_sync(0xffffffffu, v, 16);
            v += __shfl_down_sync(0xffffffffu, v, 8);
            v += __shfl_down_sync(0xffffffffu, v, 4);
            v += __shfl_down_sync(0xffffffffu, v, 2);
            v += __shfl_down_sync(0xffffffffu, v, 1);
            if (lane == 0) out[(size_t)(b0 + row) * Tt + t] = v + bo;
        }
    }
}

// ============================================================================
// launch
// ============================================================================
extern "C" void kernel_launch(void* const* d_in, const int* in_sizes, int n_in,
                              void* d_out, int out_size)
{
    const float* x_dyn = (const float*)d_in[0];
    const float* x_sta = (const float*)d_in[1];
    const float* W_ih  = (const float*)d_in[2];
    const float* W_hh  = (const float*)d_in[3];
    const float* W_zh  = (const float*)d_in[4];
    const float* bvec  = (const float*)d_in[5];
    const float* W_out = (const float*)d_in[6];
    const float* b_out = (const float*)d_in[7];
    float* out = (float*)d_out;

    (void)in_sizes; (void)n_in; (void)out_size;

    cudaFuncSetAttribute(pre_kernel,
                         cudaFuncAttributeMaxDynamicSharedMemorySize, PRE_SMEM);
    cudaFuncSetAttribute(scan_kernel,
                         cudaFuncAttributeMaxDynamicSharedMemorySize, SCAN_SMEM);

    dim3 pre_grid((Bb * Tt) / PRE_MT, G4 / PRE_NT);   // 2048 x 4
    pre_kernel<<<pre_grid, 256, PRE_SMEM>>>(x_dyn, W_ih, x_sta, W_zh, bvec);

    scan_kernel<<<128, 512, SCAN_SMEM>>>(W_hh, W_out, b_out, out);
}

// round 13
// speedup vs baseline: 1.7587x; 1.0581x over previous
#include <cuda_runtime.h>
#include <cuda_fp16.h>
#include <cstdint>
#include <cstddef>

// Problem dims (fixed by reference)
#define Bb 256
#define Tt 512
#define Dd 64
#define Ll 32
#define Hh 128
#define G4 512   // 4*H

// ---------------- scratch (device globals; no allocation allowed) ----------
__device__ float g_pre[(size_t)Bb * Tt * G4];   // 268 MB: pre-activations

// ---------------- math helpers ---------------------------------------------
__device__ __forceinline__ float sigf(float x) {
    return __fdividef(1.0f, 1.0f + __expf(-x));
}
__device__ __forceinline__ float tanhf_fast(float x) {
    x = fminf(20.0f, fmaxf(-20.0f, x));
    float e = __expf(-2.0f * x);
    return __fdividef(1.0f - e, 1.0f + e);
}

// ============================================================================
// Kernel 1: pre-GEMM, HFMA2 round.
//   g_pre[m][n] = sum_k x[m][k]*Wih[n][k] + (x_static@Wzh^T + b)[n]
//   fp16 x tile [64 m][64 k] (pad 66) + fp16 W tile TRANSPOSED [64 k][128 n]
//   (n-pairs contiguous -> LDS.32 half2, k warp-uniform -> conflict-free).
//   Two fp16 accumulation chains per output (even/odd k), merged in fp32.
//   1024 HFMA2 vs 2048 FFMA per thread; W crossbar bytes halved.
// ============================================================================
#define PRE_MT 64
#define PRE_NT 128
#define PADX 66
// half-index offsets in dynamic smem
#define OFF_X16  0                       // 64*66 = 4224 halfs
#define OFF_W16  4224                    // 64*128 = 8192 halfs
#define OFF_SV   ((4224 + 8192) / 2)     // float index 6208: svrow[128]
#define PRE_SMEM ((OFF_SV + 128) * 4)    // 25344 bytes

__global__ __launch_bounds__(256) void pre_kernel(
    const float* __restrict__ xd, const float* __restrict__ Wih,
    const float* __restrict__ xs, const float* __restrict__ Wzh,
    const float* __restrict__ bvec)
{
    extern __shared__ float sm[];
    __half* xsm = (__half*)sm + OFF_X16;     // [64 m][66 (64 k used)]
    __half* wsm = (__half*)sm + OFF_W16;     // [64 k][128 n]
    float*  svrow = sm + OFF_SV;             // [128]

    int t  = threadIdx.x;
    int m0 = blockIdx.x * PRE_MT;
    int n0 = blockIdx.y * PRE_NT;
    int bb = m0 >> 9;   // T = 512

    // x tile -> fp16 (coalesced float4 loads, half2 stores)
    {
        const float4* xg = (const float4*)(xd + (size_t)m0 * Dd);
        for (int i = t; i < PRE_MT * (Dd / 4); i += 256) {
            int row = i >> 4, dq = i & 15;
            float4 v = xg[row * 16 + dq];
            __half2 h0 = __floats2half2_rn(v.x, v.y);
            __half2 h1 = __floats2half2_rn(v.z, v.w);
            __half* dst = xsm + row * PADX + dq * 4;
            *(__half2*)(dst)     = h0;
            *(__half2*)(dst + 2) = h1;
        }
    }
    // W tile -> fp16 TRANSPOSED [k][n] (scalar half scatter; setup-only cost)
    {
        for (int i = t; i < PRE_NT * (Dd / 4); i += 256) {
            int n  = i & 127;
            int kq = i >> 7;
            float4 v = *(const float4*)(Wih + (size_t)(n0 + n) * Dd + kq * 4);
            wsm[(kq * 4 + 0) * 128 + n] = __float2half_rn(v.x);
            wsm[(kq * 4 + 1) * 128 + n] = __float2half_rn(v.y);
            wsm[(kq * 4 + 2) * 128 + n] = __float2half_rn(v.z);
            wsm[(kq * 4 + 3) * 128 + n] = __float2half_rn(v.w);
        }
    }
    // fused static part (fp32, exact)
    if (t < PRE_NT) {
        int gn = n0 + t;
        float acc = bvec[gn];
        const float* w = Wzh + gn * Ll;
        const float* xr = xs + bb * Ll;
#pragma unroll
        for (int l = 0; l < Ll; l++) acc += xr[l] * w[l];
        svrow[t] = acc;
    }
    __syncthreads();

    int tn = t & 15;   // n pair base: n = tn*2 + 32*jj
    int tm = t >> 4;   // m = tm + 16*i

    __half2 accE[16], accO[16];   // [i][jj] -> i*4+jj ; even/odd k chains
    const __half2 z2 = __float2half2_rn(0.0f);
#pragma unroll
    for (int q = 0; q < 16; q++) { accE[q] = z2; accO[q] = z2; }

#pragma unroll 8
    for (int kk = 0; kk < 32; kk++) {     // k = 2*kk, 2*kk+1
        __half2 aE[4], aO[4];
#pragma unroll
        for (int i = 0; i < 4; i++) {
            __half2 xv = *(const __half2*)(xsm + (tm + 16 * i) * PADX + 2 * kk);
            aE[i] = __low2half2(xv);
            aO[i] = __high2half2(xv);
        }
        __half2 bE[4], bO[4];
#pragma unroll
        for (int jj = 0; jj < 4; jj++) {
            bE[jj] = *(const __half2*)(wsm + (2 * kk)     * 128 + tn * 2 + 32 * jj);
            bO[jj] = *(const __half2*)(wsm + (2 * kk + 1) * 128 + tn * 2 + 32 * jj);
        }
#pragma unroll
        for (int i = 0; i < 4; i++)
#pragma unroll
            for (int jj = 0; jj < 4; jj++) {
                accE[i * 4 + jj] = __hfma2(aE[i], bE[jj], accE[i * 4 + jj]);
                accO[i * 4 + jj] = __hfma2(aO[i], bO[jj], accO[i * 4 + jj]);
            }
    }

    // Epilogue: merge chains in fp32, add static, 8B stores
#pragma unroll
    for (int i = 0; i < 4; i++) {
        float* orow = g_pre + (size_t)(m0 + tm + 16 * i) * G4 + n0;
#pragma unroll
        for (int jj = 0; jj < 4; jj++) {
            int n = tn * 2 + 32 * jj;
            float2 e = __half22float2(accE[i * 4 + jj]);
            float2 o = __half22float2(accO[i * 4 + jj]);
            float2 s = *(const float2*)(svrow + n);
            float2 r;
            r.x = (e.x + o.x) + s.x;
            r.y = (e.y + o.y) + s.y;
            *(float2*)(orow + n) = r;
        }
    }
}

// ============================================================================
// Kernel 2: persistent LSTM scan — UNCHANGED from R12 (1030us best:
//   HFMA2 matvec, fp16 W smem + half2 W regs, fp16 h, acts in matvec threads,
//   O-head off the critical path on warps 8,9).
// ============================================================================
#define NWCH 12   // fp16 W chunks of 8 d-values (d 0..95)
#define OFF_WH   0                        // 12*512*8 halfs = 24576 floats
#define OFF_H16  24576                    // h16[2][128] fp16 = 128 floats
#define OFF_G    (OFF_H16 + 128)          // act[2][512] fp32
#define SCAN_SMEM ((OFF_G + 1024) * 4)    // 102912 bytes

__global__ void __launch_bounds__(512, 1)
scan_kernel(const float* __restrict__ Whh, const float* __restrict__ Wout,
            const float* __restrict__ bout, float* __restrict__ out)
{
    extern __shared__ float sm[];
    __half* whsm = (__half*)(sm + OFF_WH);    // [12 chunks][512 j][8 d] fp16
    __half* h16  = (__half*)(sm + OFF_H16);   // [2 rows][128 d] fp16
    int tid  = threadIdx.x;
    int b0   = blockIdx.x * 2;
    int j    = tid;                // gate-column index 0..511
    int wrp  = tid >> 5;
    int lane = tid & 31;
    bool is_tanh_gate = ((j >> 7) == 2);   // warp-uniform

    // ---- W d 0..95 -> fp16 smem: whsm[c][j][0..7]
#pragma unroll
    for (int c = 0; c < NWCH; c++) {
        float4 va = *(const float4*)(Whh + (size_t)j * 128 + c * 8);
        float4 vb = *(const float4*)(Whh + (size_t)j * 128 + c * 8 + 4);
        __half2 p0 = __floats2half2_rn(va.x, va.y);
        __half2 p1 = __floats2half2_rn(va.z, va.w);
        __half2 p2 = __floats2half2_rn(vb.x, vb.y);
        __half2 p3 = __floats2half2_rn(vb.z, vb.w);
        uint4 pk;
        pk.x = *(uint32_t*)&p0; pk.y = *(uint32_t*)&p1;
        pk.z = *(uint32_t*)&p2; pk.w = *(uint32_t*)&p3;
        *(uint4*)(whsm + (size_t)c * 4096 + j * 8) = pk;
    }
    // ---- W d 96..127 as 16 half2 registers
    __half2 whr[16];
    {
        const float* ws = Whh + (size_t)j * 128 + 96;
#pragma unroll
        for (int c = 0; c < 16; c++)
            whr[c] = __floats2half2_rn(ws[2 * c], ws[2 * c + 1]);
    }
    if (tid < 256) h16[tid] = __float2half(0.0f);
    __syncthreads();

    int r2 = tid >> 7;        // row 0..1 (update role, tid < 256)
    int k  = tid & 127;       // hidden index (update role)

    float cst = 0.0f;
    float bo  = bout[0];
    float4 wo4 = make_float4(0.f, 0.f, 0.f, 0.f);
    if (wrp == 8 || wrp == 9) wo4 = *(const float4*)(Wout + lane * 4);

    const float* pre0 = g_pre + ((size_t)(b0 + 0) * Tt) * G4 + j;
    const float* pre1 = g_pre + ((size_t)(b0 + 1) * Tt) * G4 + j;

    const __half2 z2 = __float2half2_rn(0.0f);

    for (int t = 0; t < Tt; t++) {
        float p0 = pre0[(size_t)t * G4];
        float p1 = pre1[(size_t)t * G4];

        __half2 acc0[4], acc1[4];
#pragma unroll
        for (int i = 0; i < 4; i++) { acc0[i] = z2; acc1[i] = z2; }

#pragma unroll
        for (int c = 0; c < NWCH; c++) {         // d 0..95 (fp16 smem weights)
            uint4 wp  = *(const uint4*)(whsm + (size_t)c * 4096 + j * 8);
            uint4 hp0 = *(const uint4*)(h16 + c * 8);
            uint4 hp1 = *(const uint4*)(h16 + 128 + c * 8);
            const __half2* w2 = (const __half2*)&wp;
            const __half2* a2 = (const __half2*)&hp0;
            const __half2* b2 = (const __half2*)&hp1;
            int ai = c & 3;
#pragma unroll
            for (int q = 0; q < 4; q++) {
                acc0[ai] = __hfma2(w2[q], a2[q], acc0[ai]);
                acc1[ai] = __hfma2(w2[q], b2[q], acc1[ai]);
            }
        }
#pragma unroll
        for (int c = 0; c < 4; c++) {            // d 96..127 (register weights)
            uint4 hp0 = *(const uint4*)(h16 + 96 + c * 8);
            uint4 hp1 = *(const uint4*)(h16 + 128 + 96 + c * 8);
            const __half2* a2 = (const __half2*)&hp0;
            const __half2* b2 = (const __half2*)&hp1;
#pragma unroll
            for (int q = 0; q < 4; q++) {
                acc0[c] = __hfma2(whr[4 * c + q], a2[q], acc0[c]);
                acc1[c] = __hfma2(whr[4 * c + q], b2[q], acc1[c]);
            }
        }
        float2 m00 = __half22float2(acc0[0]), m01 = __half22float2(acc0[1]);
        float2 m02 = __half22float2(acc0[2]), m03 = __half22float2(acc0[3]);
        float2 m10 = __half22float2(acc1[0]), m11 = __half22float2(acc1[1]);
        float2 m12 = __half22float2(acc1[2]), m13 = __half22float2(acc1[3]);
        float g0 = p0 + ((m00.x + m00.y) + (m01.x + m01.y))
                      + ((m02.x + m02.y) + (m03.x + m03.y));
        float g1 = p1 + ((m10.x + m10.y) + (m11.x + m11.y))
                      + ((m12.x + m12.y) + (m13.x + m13.y));

        float act0, act1;
        if (is_tanh_gate) { act0 = tanhf_fast(g0); act1 = tanhf_fast(g1); }
        else              { act0 = sigf(g0);       act1 = sigf(g1);       }
        sm[OFF_G + 0 * 512 + j] = act0;
        sm[OFF_G + 1 * 512 + j] = act1;
        __syncthreads();   // barrier 1: acts visible

        if (tid < 256) {
            float ai = sm[OFF_G + r2 * 512 + k];
            float af = sm[OFF_G + r2 * 512 + 128 + k];
            float ag = sm[OFF_G + r2 * 512 + 256 + k];
            float ao = sm[OFF_G + r2 * 512 + 384 + k];
            cst = af * cst + ai * ag;
            float hval = ao * tanhf_fast(cst);
            h16[r2 * 128 + k] = __float2half(hval);
        }
        __syncthreads();   // barrier 2: h16 ready

        if (wrp == 8 || wrp == 9) {
            int row = wrp - 8;
            float2 ha = __half22float2(*(const __half2*)(h16 + row * 128 + lane * 4));
            float2 hb = __half22float2(*(const __half2*)(h16 + row * 128 + lane * 4 + 2));
            float v = ha.x * wo4.x + ha.y * wo4.y + hb.x * wo4.z + hb.y * wo4.w;
            v += __shfl_down_sync(0xffffffffu, v, 16);
            v += __shfl_down_sync(0xffffffffu, v, 8);
            v += __shfl_down_sync(0xffffffffu, v, 4);
            v += __shfl_down_sync(0xffffffffu, v, 2);
            v += __shfl_down_sync(0xffffffffu, v, 1);
            if (lane == 0) out[(size_t)(b0 + row) * Tt + t] = v + bo;
        }
    }
}

// ============================================================================
// launch
// ============================================================================
extern "C" void kernel_launch(void* const* d_in, const int* in_sizes, int n_in,
                              void* d_out, int out_size)
{
    const float* x_dyn = (const float*)d_in[0];
    const float* x_sta = (const float*)d_in[1];
    const float* W_ih  = (const float*)d_in[2];
    const float* W_hh  = (const float*)d_in[3];
    const float* W_zh  = (const float*)d_in[4];
    const float* bvec  = (const float*)d_in[5];
    const float* W_out = (const float*)d_in[6];
    const float* b_out = (const float*)d_in[7];
    float* out = (float*)d_out;

    (void)in_sizes; (void)n_in; (void)out_size;

    cudaFuncSetAttribute(pre_kernel,
                         cudaFuncAttributeMaxDynamicSharedMemorySize, PRE_SMEM);
    cudaFuncSetAttribute(scan_kernel,
                         cudaFuncAttributeMaxDynamicSharedMemorySize, SCAN_SMEM);

    dim3 pre_grid((Bb * Tt) / PRE_MT, G4 / PRE_NT);   // 2048 x 4
    pre_kernel<<<pre_grid, 256, PRE_SMEM>>>(x_dyn, W_ih, x_sta, W_zh, bvec);

    scan_kernel<<<128, 512, SCAN_SMEM>>>(W_hh, W_out, b_out, out);
}

// round 14
// speedup vs baseline: 1.9256x; 1.0949x over previous
#include <cuda_runtime.h>
#include <cuda_fp16.h>
#include <cstdint>
#include <cstddef>

// Problem dims (fixed by reference)
#define Bb 256
#define Tt 512
#define Dd 64
#define Ll 32
#define Hh 128
#define G4 512   // 4*H

// ---------------- scratch (device globals; no allocation allowed) ----------
__device__ float g_pre[(size_t)Bb * Tt * G4];   // 268 MB: pre-activations

// ---------------- math helpers ---------------------------------------------
__device__ __forceinline__ float sigf(float x) {
    return __fdividef(1.0f, 1.0f + __expf(-x));
}
__device__ __forceinline__ float tanhf_fast(float x) {
    x = fminf(20.0f, fmaxf(-20.0f, x));
    float e = __expf(-2.0f * x);
    return __fdividef(1.0f - e, 1.0f + e);
}

// HMMA m16n8k16, fp16 inputs, fp32 accumulate
__device__ __forceinline__ void mma16816(
    float& c0, float& c1, float& c2, float& c3,
    uint32_t a0, uint32_t a1, uint32_t a2, uint32_t a3,
    uint32_t b0, uint32_t b1)
{
    asm volatile(
        "mma.sync.aligned.m16n8k16.row.col.f32.f16.f16.f32 "
        "{%0,%1,%2,%3}, {%4,%5,%6,%7}, {%8,%9}, {%0,%1,%2,%3};"
        : "+f"(c0), "+f"(c1), "+f"(c2), "+f"(c3)
        : "r"(a0), "r"(a1), "r"(a2), "r"(a3), "r"(b0), "r"(b1));
}

// ============================================================================
// Kernel 1: pre-GEMM on the TENSOR pipe (mma.sync, fp32 accumulate).
//   g_pre[m][n] = sum_k x[m][k]*Wih[n][k] + (x_static@Wzh^T + b)[n]
//   CTA: 256 thr / 8 warps; tile M64 x N128 (warps 4M x 2N, warp M16 x N64).
//   x tile fp16 [64 m][72], W tile fp16 [128 n][72] (Wih is [n][k] row-major
//   = the col-major B operand directly — no transpose).
//   fp16 only at inputs; accumulation exact fp32 -> pre-act err ~1e-4.
// ============================================================================
#define PRE_MT 64
#define PRE_NT 128
#define XSTR 72
// half-index offsets in dynamic smem
#define OFF_X16  0                       // 64*72 = 4608 halfs
#define OFF_W16  4608                    // 128*72 = 9216 halfs
#define OFF_SV   ((4608 + 9216) / 2)     // float index 6912
#define PRE_SMEM ((OFF_SV + 128) * 4)    // 28160 bytes

__global__ __launch_bounds__(256) void pre_kernel(
    const float* __restrict__ xd, const float* __restrict__ Wih,
    const float* __restrict__ xs, const float* __restrict__ Wzh,
    const float* __restrict__ bvec)
{
    extern __shared__ float sm[];
    __half* xsm = (__half*)sm + OFF_X16;     // [64 m][72 (64 k used)]
    __half* wsm = (__half*)sm + OFF_W16;     // [128 n][72 (64 k used)]
    float*  svrow = sm + OFF_SV;             // [128]

    int t  = threadIdx.x;
    int m0 = blockIdx.x * PRE_MT;
    int n0 = blockIdx.y * PRE_NT;
    int bb = m0 >> 9;   // T = 512

    // x tile -> fp16 (coalesced float4 loads, half2 stores)
    {
        const float4* xg = (const float4*)(xd + (size_t)m0 * Dd);
#pragma unroll
        for (int i = t; i < PRE_MT * (Dd / 4); i += 256) {
            int row = i >> 4, dq = i & 15;
            float4 v = xg[row * 16 + dq];
            __half* dst = xsm + row * XSTR + dq * 4;
            *(__half2*)(dst)     = __floats2half2_rn(v.x, v.y);
            *(__half2*)(dst + 2) = __floats2half2_rn(v.z, v.w);
        }
    }
    // W tile -> fp16, same [n][k] layout (no transpose)
    {
        const float4* wg = (const float4*)(Wih + (size_t)n0 * Dd);
#pragma unroll
        for (int i = t; i < PRE_NT * (Dd / 4); i += 256) {
            int row = i >> 4, dq = i & 15;
            float4 v = wg[row * 16 + dq];
            __half* dst = wsm + row * XSTR + dq * 4;
            *(__half2*)(dst)     = __floats2half2_rn(v.x, v.y);
            *(__half2*)(dst + 2) = __floats2half2_rn(v.z, v.w);
        }
    }
    // fused static part (fp32, exact)
    if (t < PRE_NT) {
        int gn = n0 + t;
        float acc = bvec[gn];
        const float* w = Wzh + gn * Ll;
        const float* xr = xs + bb * Ll;
#pragma unroll
        for (int l = 0; l < Ll; l++) acc += xr[l] * w[l];
        svrow[t] = acc;
    }
    __syncthreads();

    int wid  = t >> 5;
    int lane = t & 31;
    int wm   = wid >> 1;           // 0..3: warp m-row (16 rows each)
    int wn   = wid & 1;            // 0..1: warp n-col (64 cols each)
    int r    = lane >> 2;          // 0..7
    int cq   = (lane & 3) * 2;     // 0,2,4,6

    float c[8][4];
#pragma unroll
    for (int nf = 0; nf < 8; nf++)
#pragma unroll
        for (int q = 0; q < 4; q++) c[nf][q] = 0.0f;

    const __half* xw = xsm + (wm * 16 + r) * XSTR;

#pragma unroll
    for (int kc = 0; kc < 4; kc++) {
        int kb = kc * 16 + cq;
        uint32_t a0 = *(const uint32_t*)(xw + kb);               // A[r][k..k+1]
        uint32_t a1 = *(const uint32_t*)(xw + 8 * XSTR + kb);    // A[r+8][..]
        uint32_t a2 = *(const uint32_t*)(xw + kb + 8);           // A[r][k+8..]
        uint32_t a3 = *(const uint32_t*)(xw + 8 * XSTR + kb + 8);
#pragma unroll
        for (int nf = 0; nf < 8; nf++) {
            const __half* bp = wsm + (wn * 64 + nf * 8 + r) * XSTR + kb;
            uint32_t b0 = *(const uint32_t*)(bp);       // B[k..k+1][n]
            uint32_t b1 = *(const uint32_t*)(bp + 8);   // B[k+8..k+9][n]
            mma16816(c[nf][0], c[nf][1], c[nf][2], c[nf][3],
                     a0, a1, a2, a3, b0, b1);
        }
    }

    // Epilogue: add static, store float2 pairs (rows r and r+8)
    int m_base = m0 + wm * 16 + r;
#pragma unroll
    for (int nf = 0; nf < 8; nf++) {
        int n_loc = wn * 64 + nf * 8 + cq;
        float2 sv = *(const float2*)(svrow + n_loc);
        float* gp0 = g_pre + (size_t)m_base * G4 + n0 + n_loc;
        float* gp1 = g_pre + (size_t)(m_base + 8) * G4 + n0 + n_loc;
        float2 r0; r0.x = c[nf][0] + sv.x; r0.y = c[nf][1] + sv.y;
        float2 r1; r1.x = c[nf][2] + sv.x; r1.y = c[nf][3] + sv.y;
        *(float2*)gp0 = r0;
        *(float2*)gp1 = r1;
    }
}

// ============================================================================
// Kernel 2: persistent LSTM scan — UNCHANGED (R12/R13 body, 685us):
//   HFMA2 matvec, fp16 W smem + half2 W regs, fp16 h, acts in matvec threads,
//   O-head off the critical path on warps 8,9.
// ============================================================================
#define NWCH 12   // fp16 W chunks of 8 d-values (d 0..95)
#define OFF_WH   0                        // 12*512*8 halfs = 24576 floats
#define OFF_H16  24576                    // h16[2][128] fp16 = 128 floats
#define OFF_G    (OFF_H16 + 128)          // act[2][512] fp32
#define SCAN_SMEM ((OFF_G + 1024) * 4)    // 102912 bytes

__global__ void __launch_bounds__(512, 1)
scan_kernel(const float* __restrict__ Whh, const float* __restrict__ Wout,
            const float* __restrict__ bout, float* __restrict__ out)
{
    extern __shared__ float sm[];
    __half* whsm = (__half*)(sm + OFF_WH);    // [12 chunks][512 j][8 d] fp16
    __half* h16  = (__half*)(sm + OFF_H16);   // [2 rows][128 d] fp16
    int tid  = threadIdx.x;
    int b0   = blockIdx.x * 2;
    int j    = tid;                // gate-column index 0..511
    int wrp  = tid >> 5;
    int lane = tid & 31;
    bool is_tanh_gate = ((j >> 7) == 2);   // warp-uniform

    // ---- W d 0..95 -> fp16 smem: whsm[c][j][0..7]
#pragma unroll
    for (int c = 0; c < NWCH; c++) {
        float4 va = *(const float4*)(Whh + (size_t)j * 128 + c * 8);
        float4 vb = *(const float4*)(Whh + (size_t)j * 128 + c * 8 + 4);
        __half2 p0 = __floats2half2_rn(va.x, va.y);
        __half2 p1 = __floats2half2_rn(va.z, va.w);
        __half2 p2 = __floats2half2_rn(vb.x, vb.y);
        __half2 p3 = __floats2half2_rn(vb.z, vb.w);
        uint4 pk;
        pk.x = *(uint32_t*)&p0; pk.y = *(uint32_t*)&p1;
        pk.z = *(uint32_t*)&p2; pk.w = *(uint32_t*)&p3;
        *(uint4*)(whsm + (size_t)c * 4096 + j * 8) = pk;
    }
    // ---- W d 96..127 as 16 half2 registers
    __half2 whr[16];
    {
        const float* ws = Whh + (size_t)j * 128 + 96;
#pragma unroll
        for (int c = 0; c < 16; c++)
            whr[c] = __floats2half2_rn(ws[2 * c], ws[2 * c + 1]);
    }
    if (tid < 256) h16[tid] = __float2half(0.0f);
    __syncthreads();

    int r2 = tid >> 7;        // row 0..1 (update role, tid < 256)
    int k  = tid & 127;       // hidden index (update role)

    float cst = 0.0f;
    float bo  = bout[0];
    float4 wo4 = make_float4(0.f, 0.f, 0.f, 0.f);
    if (wrp == 8 || wrp == 9) wo4 = *(const float4*)(Wout + lane * 4);

    const float* pre0 = g_pre + ((size_t)(b0 + 0) * Tt) * G4 + j;
    const float* pre1 = g_pre + ((size_t)(b0 + 1) * Tt) * G4 + j;

    const __half2 z2 = __float2half2_rn(0.0f);

    for (int t = 0; t < Tt; t++) {
        float p0 = pre0[(size_t)t * G4];
        float p1 = pre1[(size_t)t * G4];

        __half2 acc0[4], acc1[4];
#pragma unroll
        for (int i = 0; i < 4; i++) { acc0[i] = z2; acc1[i] = z2; }

#pragma unroll
        for (int c = 0; c < NWCH; c++) {         // d 0..95 (fp16 smem weights)
            uint4 wp  = *(const uint4*)(whsm + (size_t)c * 4096 + j * 8);
            uint4 hp0 = *(const uint4*)(h16 + c * 8);
            uint4 hp1 = *(const uint4*)(h16 + 128 + c * 8);
            const __half2* w2 = (const __half2*)&wp;
            const __half2* a2 = (const __half2*)&hp0;
            const __half2* b2 = (const __half2*)&hp1;
            int ai = c & 3;
#pragma unroll
            for (int q = 0; q < 4; q++) {
                acc0[ai] = __hfma2(w2[q], a2[q], acc0[ai]);
                acc1[ai] = __hfma2(w2[q], b2[q], acc1[ai]);
            }
        }
#pragma unroll
        for (int c = 0; c < 4; c++) {            // d 96..127 (register weights)
            uint4 hp0 = *(const uint4*)(h16 + 96 + c * 8);
            uint4 hp1 = *(const uint4*)(h16 + 128 + 96 + c * 8);
            const __half2* a2 = (const __half2*)&hp0;
            const __half2* b2 = (const __half2*)&hp1;
#pragma unroll
            for (int q = 0; q < 4; q++) {
                acc0[c] = __hfma2(whr[4 * c + q], a2[q], acc0[c]);
                acc1[c] = __hfma2(whr[4 * c + q], b2[q], acc1[c]);
            }
        }
        float2 m00 = __half22float2(acc0[0]), m01 = __half22float2(acc0[1]);
        float2 m02 = __half22float2(acc0[2]), m03 = __half22float2(acc0[3]);
        float2 m10 = __half22float2(acc1[0]), m11 = __half22float2(acc1[1]);
        float2 m12 = __half22float2(acc1[2]), m13 = __half22float2(acc1[3]);
        float g0 = p0 + ((m00.x + m00.y) + (m01.x + m01.y))
                      + ((m02.x + m02.y) + (m03.x + m03.y));
        float g1 = p1 + ((m10.x + m10.y) + (m11.x + m11.y))
                      + ((m12.x + m12.y) + (m13.x + m13.y));

        float act0, act1;
        if (is_tanh_gate) { act0 = tanhf_fast(g0); act1 = tanhf_fast(g1); }
        else              { act0 = sigf(g0);       act1 = sigf(g1);       }
        sm[OFF_G + 0 * 512 + j] = act0;
        sm[OFF_G + 1 * 512 + j] = act1;
        __syncthreads();   // barrier 1: acts visible

        if (tid < 256) {
            float ai = sm[OFF_G + r2 * 512 + k];
            float af = sm[OFF_G + r2 * 512 + 128 + k];
            float ag = sm[OFF_G + r2 * 512 + 256 + k];
            float ao = sm[OFF_G + r2 * 512 + 384 + k];
            cst = af * cst + ai * ag;
            float hval = ao * tanhf_fast(cst);
            h16[r2 * 128 + k] = __float2half(hval);
        }
        __syncthreads();   // barrier 2: h16 ready

        if (wrp == 8 || wrp == 9) {
            int row = wrp - 8;
            float2 ha = __half22float2(*(const __half2*)(h16 + row * 128 + lane * 4));
            float2 hb = __half22float2(*(const __half2*)(h16 + row * 128 + lane * 4 + 2));
            float v = ha.x * wo4.x + ha.y * wo4.y + hb.x * wo4.z + hb.y * wo4.w;
            v += __shfl_down_sync(0xffffffffu, v, 16);
            v += __shfl_down_sync(0xffffffffu, v, 8);
            v += __shfl_down_sync(0xffffffffu, v, 4);
            v += __shfl_down_sync(0xffffffffu, v, 2);
            v += __shfl_down_sync(0xffffffffu, v, 1);
            if (lane == 0) out[(size_t)(b0 + row) * Tt + t] = v + bo;
        }
    }
}

// ============================================================================
// launch
// ============================================================================
extern "C" void kernel_launch(void* const* d_in, const int* in_sizes, int n_in,
                              void* d_out, int out_size)
{
    const float* x_dyn = (const float*)d_in[0];
    const float* x_sta = (const float*)d_in[1];
    const float* W_ih  = (const float*)d_in[2];
    const float* W_hh  = (const float*)d_in[3];
    const float* W_zh  = (const float*)d_in[4];
    const float* bvec  = (const float*)d_in[5];
    const float* W_out = (const float*)d_in[6];
    const float* b_out = (const float*)d_in[7];
    float* out = (float*)d_out;

    (void)in_sizes; (void)n_in; (void)out_size;

    cudaFuncSetAttribute(pre_kernel,
                         cudaFuncAttributeMaxDynamicSharedMemorySize, PRE_SMEM);
    cudaFuncSetAttribute(scan_kernel,
                         cudaFuncAttributeMaxDynamicSharedMemorySize, SCAN_SMEM);

    dim3 pre_grid((Bb * Tt) / PRE_MT, G4 / PRE_NT);   // 2048 x 4
    pre_kernel<<<pre_grid, 256, PRE_SMEM>>>(x_dyn, W_ih, x_sta, W_zh, bvec);

    scan_kernel<<<128, 512, SCAN_SMEM>>>(W_hh, W_out, b_out, out);
}